// round 1
// baseline (speedup 1.0000x reference)
#include <cuda_runtime.h>
#include <cuda_fp16.h>

// Problem constants
#define HEADS    4
#define B_TOT    256          // n * heads = 64 * 4
#define IN_SIZE  1024
#define IN_DIM   128
#define OUT_SIZE 64
#define ITERS    100

// Scratch: M = exp(K), fp16, quad-interleaved per batch:
//   element (b, o, s) at d_M[b*65536 + (o>>2)*4096 + s*4 + (o&3)]
__device__ __half d_M[(size_t)B_TOT * IN_SIZE * OUT_SIZE];

// ---------------------------------------------------------------------------
// Kernel 1: K[b,s,o] = sum_d x[n,s,d] * w[m,o,d];  M = exp(K) -> d_M (fp16)
// Grid: (16 s-tiles, 256 batches). Block: 256 threads, thread tile 4s x 4o.
// ---------------------------------------------------------------------------
__global__ __launch_bounds__(256) void gemm_exp_kernel(
    const float* __restrict__ x, const float* __restrict__ w)
{
    const int stile = blockIdx.x;      // 0..15
    const int b     = blockIdx.y;      // 0..255
    const int n = b >> 2, m = b & 3;
    const int t  = threadIdx.x;
    const int si = t & 15;             // s-lane (keeps stores coalesced)
    const int oi = t >> 4;             // o-quad 0..15

    float acc[4][4];
#pragma unroll
    for (int i = 0; i < 4; i++)
#pragma unroll
        for (int j = 0; j < 4; j++) acc[i][j] = 0.f;

    const float* xb = x + ((size_t)n * IN_SIZE + stile * 64) * IN_DIM;
    const float* wb = w + ((size_t)m * OUT_SIZE) * IN_DIM;

#pragma unroll 2
    for (int d = 0; d < IN_DIM; d += 4) {
        float4 xv[4], wv[4];
#pragma unroll
        for (int i = 0; i < 4; i++)
            xv[i] = *(const float4*)(xb + (si + 16 * i) * IN_DIM + d);
#pragma unroll
        for (int j = 0; j < 4; j++)
            wv[j] = *(const float4*)(wb + (oi * 4 + j) * IN_DIM + d);
#pragma unroll
        for (int i = 0; i < 4; i++)
#pragma unroll
            for (int j = 0; j < 4; j++)
                acc[i][j] += xv[i].x * wv[j].x + xv[i].y * wv[j].y +
                             xv[i].z * wv[j].z + xv[i].w * wv[j].w;
    }

    __half* Mb = d_M + (size_t)b * (IN_SIZE * OUT_SIZE);
#pragma unroll
    for (int i = 0; i < 4; i++) {
        const int s = stile * 64 + si + 16 * i;
        __half2 h0 = __floats2half2_rn(__expf(acc[i][0]), __expf(acc[i][1]));
        __half2 h1 = __floats2half2_rn(__expf(acc[i][2]), __expf(acc[i][3]));
        uint2 pk;
        pk.x = *reinterpret_cast<unsigned int*>(&h0);
        pk.y = *reinterpret_cast<unsigned int*>(&h1);
        // 4 consecutive halves (one o-quad) -> one 8B store, lanes si coalesced
        *(uint2*)(Mb + oi * 4096 + s * 4) = pk;
    }
}

// ---------------------------------------------------------------------------
// Kernel 2: per-batch multiplicative Sinkhorn (100 iters, M smem-resident)
// then fused output GEMM:  out[n,o,m*128+d] = c_o * sum_s r_s M[s,o] x[n,s,d]
// Grid: 256 CTAs (one per batch). Block: 1024 threads.
// Dynamic smem: Mt 128KB | xs 32KB | r 4KB | c 256B | part 512B = 168704 B
// ---------------------------------------------------------------------------
__global__ __launch_bounds__(1024, 1) void sinkhorn_kernel(
    const float* __restrict__ x, float* __restrict__ out)
{
    extern __shared__ char smraw[];
    __half* Mt   = (__half*)smraw;                                   // 65536 halves
    float*  xs   = (float*)(smraw + 131072);                         // 8192 floats
    float*  rv   = (float*)(smraw + 131072 + 32768);                 // 1024
    float*  cv   = (float*)(smraw + 131072 + 32768 + 4096);          // 64
    float*  part = (float*)(smraw + 131072 + 32768 + 4096 + 256);    // 128

    const int b = blockIdx.x;
    const int n = b >> 2, m = b & 3;
    const int t = threadIdx.x;
    const int lane = t & 31, warp = t >> 5;

    // Load M tile (131072 B) -> smem, layout-identical copy
    {
        const uint4* src = (const uint4*)(d_M + (size_t)b * 65536);
        uint4* dst = (uint4*)Mt;
#pragma unroll
        for (int i = 0; i < 8; i++) dst[i * 1024 + t] = src[i * 1024 + t];
    }
    if (t < 64) cv[t] = 1.0f;
    __syncthreads();

    const float A = 1.0f / 16.0f;   // row target mass = out_size/in_size

    for (int it = 0; it < ITERS; it++) {
        // ---- u-pass: thread t = row s. dot = sum_o M[s,o] * c[o]
        float dot = 0.f;
#pragma unroll
        for (int q = 0; q < 16; q++) {
            uint2 mm  = *(const uint2*)(Mt + q * 4096 + t * 4);    // 4 o's
            float4 cc = *(const float4*)(cv + q * 4);
            __half2 h0 = *reinterpret_cast<__half2*>(&mm.x);
            __half2 h1 = *reinterpret_cast<__half2*>(&mm.y);
            float2 f0 = __half22float2(h0);
            float2 f1 = __half22float2(h1);
            dot += f0.x * cc.x + f0.y * cc.y + f1.x * cc.z + f1.y * cc.w;
        }
        rv[t] = A / dot;
        __syncthreads();

        // ---- v-pass: warp -> (quad q, s-half sh). col sums over 512 rows.
        const int q = warp >> 1, sh = warp & 1;
        float s0 = 0.f, s1 = 0.f, s2 = 0.f, s3 = 0.f;
#pragma unroll
        for (int i = 0; i < 16; i++) {
            const int s = sh * 512 + i * 32 + lane;
            uint2 mm = *(const uint2*)(Mt + q * 4096 + s * 4);
            const float rr = rv[s];
            __half2 h0 = *reinterpret_cast<__half2*>(&mm.x);
            __half2 h1 = *reinterpret_cast<__half2*>(&mm.y);
            float2 f0 = __half22float2(h0);
            float2 f1 = __half22float2(h1);
            s0 += f0.x * rr; s1 += f0.y * rr; s2 += f1.x * rr; s3 += f1.y * rr;
        }
#pragma unroll
        for (int off = 16; off; off >>= 1) {
            s0 += __shfl_xor_sync(0xffffffffu, s0, off);
            s1 += __shfl_xor_sync(0xffffffffu, s1, off);
            s2 += __shfl_xor_sync(0xffffffffu, s2, off);
            s3 += __shfl_xor_sync(0xffffffffu, s3, off);
        }
        if (lane == 0) {
            float* p = part + (q * 2 + sh) * 4;
            p[0] = s0; p[1] = s1; p[2] = s2; p[3] = s3;
        }
        __syncthreads();
        if (t < 64) {
            const int qq = t >> 2, j = t & 3;
            cv[t] = 1.0f / (part[qq * 8 + j] + part[qq * 8 + 4 + j]);
        }
        __syncthreads();
    }

    // ---- fused epilogue GEMM: thread tile = 4 o (one quad) x 2 d
    const int quad = t >> 6;     // 0..15
    const int dp   = t & 63;     // d = 2*dp
    float acc[4][2];
#pragma unroll
    for (int j = 0; j < 4; j++) { acc[j][0] = 0.f; acc[j][1] = 0.f; }

    const float* xb = x + (size_t)n * IN_SIZE * IN_DIM;
    for (int sb = 0; sb < 16; sb++) {
        __syncthreads();
        // stage x[n, sb*64 .. sb*64+63, :] (32KB) into smem
        const float4* xg = (const float4*)(xb + sb * 64 * IN_DIM);
        float4* xs4 = (float4*)xs;
        xs4[t]        = xg[t];
        xs4[t + 1024] = xg[t + 1024];
        __syncthreads();
#pragma unroll 4
        for (int s = 0; s < 64; s++) {
            const int S = sb * 64 + s;
            uint2 mm = *(const uint2*)(Mt + quad * 4096 + S * 4);  // broadcast
            const float rr = rv[S];                                 // broadcast
            float2 xv = *(const float2*)(xs + s * IN_DIM + dp * 2);
            const float x0 = xv.x * rr, x1 = xv.y * rr;
            __half2 h0 = *reinterpret_cast<__half2*>(&mm.x);
            __half2 h1 = *reinterpret_cast<__half2*>(&mm.y);
            float2 f0 = __half22float2(h0);
            float2 f1 = __half22float2(h1);
            acc[0][0] += f0.x * x0; acc[0][1] += f0.x * x1;
            acc[1][0] += f0.y * x0; acc[1][1] += f0.y * x1;
            acc[2][0] += f1.x * x0; acc[2][1] += f1.x * x1;
            acc[3][0] += f1.y * x0; acc[3][1] += f1.y * x1;
        }
    }
#pragma unroll
    for (int j = 0; j < 4; j++) {
        const int o = quad * 4 + j;
        const float cval = cv[o];
        float2 res;
        res.x = acc[j][0] * cval;
        res.y = acc[j][1] * cval;
        *(float2*)(out + ((size_t)(n * 64 + o)) * 512 + m * 128 + dp * 2) = res;
    }
}

// ---------------------------------------------------------------------------
extern "C" void kernel_launch(void* const* d_in, const int* in_sizes, int n_in,
                              void* d_out, int out_size)
{
    const float* x = (const float*)d_in[0];   // [64, 1024, 128] f32
    const float* w = (const float*)d_in[1];   // [4, 64, 128] f32
    float* out = (float*)d_out;               // [64, 64, 512] f32

    const int smem_bytes = 131072 + 32768 + 4096 + 256 + 512;  // 168704
    cudaFuncSetAttribute(sinkhorn_kernel,
                         cudaFuncAttributeMaxDynamicSharedMemorySize, smem_bytes);

    dim3 g1(16, 256);
    gemm_exp_kernel<<<g1, 256>>>(x, w);
    sinkhorn_kernel<<<B_TOT, 1024, smem_bytes>>>(x, out);
}

// round 3
// speedup vs baseline: 3.0303x; 3.0303x over previous
#include <cuda_runtime.h>
#include <cuda_fp16.h>

#define IN_SIZE   1024
#define IN_DIM    128
#define OUT_SIZE  64
#define MAX_ITERS 100

// shared memory byte offsets
#define SM_MT 0                         // 65536 halves (128KB), quad-interleaved:
                                        //  (o,s) -> Mt[(o>>2)*4096 + s*4 + (o&3)]
#define SM_XS 131072                    // GEMM: [128][132] f32 padded (67584B); epilogue: [64][128] f32
#define SM_RV 198656                    // 1024 f32
#define SM_CV 202752                    // 64 f32
#define SM_FL 203008                    // 2 ints
#define SM_TOTAL 203072

__global__ __launch_bounds__(1024, 1) void ot_fused_kernel(
    const float* __restrict__ x, const float* __restrict__ w,
    float* __restrict__ out)
{
    extern __shared__ char sm[];
    __half* Mt    = (__half*)(sm + SM_MT);
    float*  xs    = (float*)(sm + SM_XS);
    float*  rv    = (float*)(sm + SM_RV);
    float*  cv    = (float*)(sm + SM_CV);
    int*    flags = (int*)(sm + SM_FL);

    const int b = blockIdx.x;
    const int n = b >> 2, m = b & 3;
    const int t = threadIdx.x;
    const int lane = t & 31, wp = t >> 5;
    const int og = t >> 6;              // 0..15  (o-quad)
    const int sl = t & 63;

    const float* xb = x + (size_t)n * IN_SIZE * IN_DIM;
    const float* wq = w + ((size_t)m * OUT_SIZE + og * 4) * IN_DIM;

    if (t == 0) { flags[0] = 0; flags[1] = 0; }
    if (t < 64) cv[t] = 1.0f;

    // ------------------------------------------------------------------
    // Phase 1: K[s,o] = x[s,:]·w[o,:];  Mt = exp(K)  (fp16, in smem)
    // 8 passes of 128 rows; thread (og, sl) computes rows {sl, sl+64} x 4 o.
    // ------------------------------------------------------------------
    for (int pr = 0; pr < 8; ++pr) {
        __syncthreads();
        const float4* xg = (const float4*)(xb + pr * 128 * IN_DIM);
#pragma unroll
        for (int jj = 0; jj < 4; ++jj) {
            int idx = jj * 1024 + t;              // 4096 float4 per pass
            float4 v = xg[idx];
            int row = idx >> 5, kq = idx & 31;
            *(float4*)(xs + row * 132 + kq * 4) = v;   // padded rows: conflict-free
        }
        __syncthreads();

        float a00=0,a01=0,a02=0,a03=0, a10=0,a11=0,a12=0,a13=0;
#pragma unroll 2
        for (int kc = 0; kc < 32; ++kc) {
            float4 xA = *(const float4*)(xs + sl        * 132 + kc * 4);
            float4 xB = *(const float4*)(xs + (sl + 64) * 132 + kc * 4);
            float4 w0 = *(const float4*)(wq + 0 * IN_DIM + kc * 4);
            float4 w1 = *(const float4*)(wq + 1 * IN_DIM + kc * 4);
            float4 w2 = *(const float4*)(wq + 2 * IN_DIM + kc * 4);
            float4 w3 = *(const float4*)(wq + 3 * IN_DIM + kc * 4);
            a00 += xA.x*w0.x + xA.y*w0.y + xA.z*w0.z + xA.w*w0.w;
            a01 += xA.x*w1.x + xA.y*w1.y + xA.z*w1.z + xA.w*w1.w;
            a02 += xA.x*w2.x + xA.y*w2.y + xA.z*w2.z + xA.w*w2.w;
            a03 += xA.x*w3.x + xA.y*w3.y + xA.z*w3.z + xA.w*w3.w;
            a10 += xB.x*w0.x + xB.y*w0.y + xB.z*w0.z + xB.w*w0.w;
            a11 += xB.x*w1.x + xB.y*w1.y + xB.z*w1.z + xB.w*w1.w;
            a12 += xB.x*w2.x + xB.y*w2.y + xB.z*w2.z + xB.w*w2.w;
            a13 += xB.x*w3.x + xB.y*w3.y + xB.z*w3.z + xB.w*w3.w;
        }
        const int S0 = pr * 128 + sl, S1 = S0 + 64;
        {
            __half2 h0 = __floats2half2_rn(__expf(a00), __expf(a01));
            __half2 h1 = __floats2half2_rn(__expf(a02), __expf(a03));
            uint2 pk; pk.x = *(unsigned*)&h0; pk.y = *(unsigned*)&h1;
            *(uint2*)(Mt + og * 4096 + S0 * 4) = pk;
        }
        {
            __half2 h0 = __floats2half2_rn(__expf(a10), __expf(a11));
            __half2 h1 = __floats2half2_rn(__expf(a12), __expf(a13));
            uint2 pk; pk.x = *(unsigned*)&h0; pk.y = *(unsigned*)&h1;
            *(uint2*)(Mt + og * 4096 + S1 * 4) = pk;
        }
    }
    __syncthreads();

    // ------------------------------------------------------------------
    // Phase 2: multiplicative Sinkhorn.  r_s = (1/16)/Σ_o M c ; c_o = 1/Σ_s M r
    // 2 barriers/iter; v-pass: warp wp owns columns {2wp, 2wp+1} over all rows.
    // Early exit when c stops changing (rel tol), deterministic per CTA.
    // ------------------------------------------------------------------
    const float A = 1.0f / 16.0f;
    const int q = wp >> 1, p = wp & 1;            // v-pass column pair
    float r = 0.f;

    for (int it = 0; it < MAX_ITERS; ++it) {
        // u-pass: thread t = row t
        float dot = 0.f;
#pragma unroll
        for (int qq = 0; qq < 16; ++qq) {
            uint2 mm  = *(const uint2*)(Mt + qq * 4096 + t * 4);
            float4 cc = *(const float4*)(cv + qq * 4);
            __half2 h0 = *(__half2*)&mm.x;
            __half2 h1 = *(__half2*)&mm.y;
            float2 f0 = __half22float2(h0);
            float2 f1 = __half22float2(h1);
            dot += f0.x*cc.x + f0.y*cc.y + f1.x*cc.z + f1.y*cc.w;
        }
        r = __fdividef(A, dot);
        rv[t] = r;
        __syncthreads();

        // v-pass: per-warp column sums over all 1024 rows
        float s0 = 0.f, s1 = 0.f;
#pragma unroll 8
        for (int i = 0; i < 32; ++i) {
            const int s = i * 32 + lane;
            unsigned mm = *(const unsigned*)(Mt + q * 4096 + s * 4 + p * 2);
            const float rr = rv[s];
            float2 f = __half22float2(*(__half2*)&mm);
            s0 += f.x * rr;
            s1 += f.y * rr;
        }
#pragma unroll
        for (int off = 16; off; off >>= 1) {
            s0 += __shfl_xor_sync(0xffffffffu, s0, off);
            s1 += __shfl_xor_sync(0xffffffffu, s1, off);
        }
        if (lane == 0) {
            const float c0 = __fdividef(1.0f, s0);
            const float c1 = __fdividef(1.0f, s1);
            const float o0 = cv[2 * wp], o1 = cv[2 * wp + 1];
            cv[2 * wp]     = c0;
            cv[2 * wp + 1] = c1;
            const float tol = 5e-7f;
            if (fabsf(c0 - o0) > tol * fabsf(o0) ||
                fabsf(c1 - o1) > tol * fabsf(o1))
                flags[it & 1] = 1;
            if (t == 0) flags[(it + 1) & 1] = 0;   // reset next-iter flag
        }
        __syncthreads();
        if (it >= 2 && flags[it & 1] == 0) break;  // converged: later ref iters are no-ops
    }

    // ------------------------------------------------------------------
    // Phase 3: fold r, c into Mt  ->  Mt holds T = diag(r) M diag(c) (fp16)
    // ------------------------------------------------------------------
#pragma unroll
    for (int qq = 0; qq < 16; ++qq) {
        uint2 mm  = *(const uint2*)(Mt + qq * 4096 + t * 4);
        float4 cc = *(const float4*)(cv + qq * 4);
        __half2 h0 = *(__half2*)&mm.x;
        __half2 h1 = *(__half2*)&mm.y;
        float2 f0 = __half22float2(h0);
        float2 f1 = __half22float2(h1);
        __half2 g0 = __floats2half2_rn(f0.x * r * cc.x, f0.y * r * cc.y);
        __half2 g1 = __floats2half2_rn(f1.x * r * cc.z, f1.y * r * cc.w);
        uint2 pk; pk.x = *(unsigned*)&g0; pk.y = *(unsigned*)&g1;
        *(uint2*)(Mt + qq * 4096 + t * 4) = pk;
    }

    // ------------------------------------------------------------------
    // Phase 4: out[n, o, m*128+d] = Σ_s T[s,o] x[s,d]
    // thread tile: 4 o (one quad) x 2 d;  x staged 64 rows at a time.
    // ------------------------------------------------------------------
    const int dp = t & 63;               // d = 2*dp
    float e00=0,e01=0,e10=0,e11=0,e20=0,e21=0,e30=0,e31=0;

    for (int sb = 0; sb < 16; ++sb) {
        __syncthreads();
        const float4* xg = (const float4*)(xb + sb * 64 * IN_DIM);
        float4* xs4 = (float4*)xs;
        xs4[t]        = xg[t];
        xs4[t + 1024] = xg[t + 1024];
        __syncthreads();
#pragma unroll 4
        for (int s = 0; s < 64; ++s) {
            const int S = sb * 64 + s;
            uint2 mm = *(const uint2*)(Mt + og * 4096 + S * 4);   // broadcast
            float2 xv = *(const float2*)(xs + s * IN_DIM + dp * 2);
            __half2 h0 = *(__half2*)&mm.x;
            __half2 h1 = *(__half2*)&mm.y;
            float2 f0 = __half22float2(h0);
            float2 f1 = __half22float2(h1);
            e00 += f0.x * xv.x;  e01 += f0.x * xv.y;
            e10 += f0.y * xv.x;  e11 += f0.y * xv.y;
            e20 += f1.x * xv.x;  e21 += f1.x * xv.y;
            e30 += f1.y * xv.x;  e31 += f1.y * xv.y;
        }
    }
    {
        float* ob = out + ((size_t)(n * 64 + og * 4)) * 512 + m * 128 + dp * 2;
        float2 r0; r0.x = e00; r0.y = e01; *(float2*)(ob)            = r0;
        float2 r1; r1.x = e10; r1.y = e11; *(float2*)(ob + 512)      = r1;
        float2 r2; r2.x = e20; r2.y = e21; *(float2*)(ob + 1024)     = r2;
        float2 r3; r3.x = e30; r3.y = e31; *(float2*)(ob + 1536)     = r3;
    }
}

// ---------------------------------------------------------------------------
extern "C" void kernel_launch(void* const* d_in, const int* in_sizes, int n_in,
                              void* d_out, int out_size)
{
    const float* x = (const float*)d_in[0];   // [64, 1024, 128] f32
    const float* w = (const float*)d_in[1];   // [4, 64, 128] f32
    float* out = (float*)d_out;               // [64, 64, 512] f32

    cudaFuncSetAttribute(ot_fused_kernel,
                         cudaFuncAttributeMaxDynamicSharedMemorySize, SM_TOTAL);
    ot_fused_kernel<<<256, 1024, SM_TOTAL>>>(x, w, out);
}